// round 1
// baseline (speedup 1.0000x reference)
#include <cuda_runtime.h>

#define ROWS 48
#define ROW_ELEMS (512 * 512)                  // 262144 elements per (b,c) row
#define CHUNKS 16
#define CHUNK_ELEMS (ROW_ELEMS / CHUNKS)       // 16384
#define THREADS 256
#define VEC_PER_THREAD (CHUNK_ELEMS / 4 / THREADS)  // 16 float4 per thread

// Per-row min/max, encoded as order-preserving uint32 for atomicMin/Max.
__device__ unsigned int g_min_enc[ROWS];
__device__ unsigned int g_max_enc[ROWS];

__device__ __forceinline__ unsigned int enc_f(float x) {
    unsigned int u = __float_as_uint(x);
    return (u & 0x80000000u) ? ~u : (u | 0x80000000u);
}
__device__ __forceinline__ float dec_f(unsigned int e) {
    unsigned int u = (e & 0x80000000u) ? (e & 0x7fffffffu) : ~e;
    return __uint_as_float(u);
}

__global__ void init_minmax_kernel() {
    int i = threadIdx.x;
    if (i < ROWS) {
        g_min_enc[i] = 0xFFFFFFFFu;  // +inf in encoded order
        g_max_enc[i] = 0x00000000u;  // -inf in encoded order
    }
}

__global__ void __launch_bounds__(THREADS) minmax_kernel(const float4* __restrict__ in) {
    const int row = blockIdx.y;
    const int chunk = blockIdx.x;
    const long base4 = (long)row * (ROW_ELEMS / 4) + (long)chunk * (CHUNK_ELEMS / 4);
    const int tid = threadIdx.x;

    float mn = 3.402823466e+38f;
    float mx = -3.402823466e+38f;

#pragma unroll
    for (int k = 0; k < VEC_PER_THREAD; k++) {
        float4 v = in[base4 + k * THREADS + tid];
        mn = fminf(mn, fminf(fminf(v.x, v.y), fminf(v.z, v.w)));
        mx = fmaxf(mx, fmaxf(fmaxf(v.x, v.y), fmaxf(v.z, v.w)));
    }

    // Warp reduce
#pragma unroll
    for (int o = 16; o > 0; o >>= 1) {
        mn = fminf(mn, __shfl_xor_sync(0xffffffffu, mn, o));
        mx = fmaxf(mx, __shfl_xor_sync(0xffffffffu, mx, o));
    }

    __shared__ float smn[THREADS / 32];
    __shared__ float smx[THREADS / 32];
    if ((tid & 31) == 0) {
        smn[tid >> 5] = mn;
        smx[tid >> 5] = mx;
    }
    __syncthreads();

    if (tid == 0) {
        float bmn = smn[0], bmx = smx[0];
#pragma unroll
        for (int w = 1; w < THREADS / 32; w++) {
            bmn = fminf(bmn, smn[w]);
            bmx = fmaxf(bmx, smx[w]);
        }
        atomicMin(&g_min_enc[row], enc_f(bmn));
        atomicMax(&g_max_enc[row], enc_f(bmx));
    }
}

// Reference-exact bound: b_j = fl32( mn + fl32( d * (j/16) ) ), j/16 exact.
__device__ __forceinline__ float bound_j(float mn, float d, int j) {
    return __fadd_rn(mn, __fmul_rn(d, (float)j * 0.0625f));
}

__global__ void __launch_bounds__(THREADS) quantize_kernel(const float4* __restrict__ in,
                                                           float4* __restrict__ out) {
    const int row = blockIdx.y;
    const int chunk = blockIdx.x;
    const long base4 = (long)row * (ROW_ELEMS / 4) + (long)chunk * (CHUNK_ELEMS / 4);
    const int tid = threadIdx.x;
    const int lane = tid & 31;

    const float mn = dec_f(g_min_enc[row]);
    const float mx = dec_f(g_max_enc[row]);
    const float d = __fadd_rn(mx, -mn);  // mx >= mn, so d = |mn - mx|

    // Degenerate test, matching float32 reference arithmetic:
    // robust_eps = 4 * FLT_EPSILON; deg = d <= robust_eps + 1e-5 * |mx|
    const float thresh = __fadd_rn(4.76837158203125e-07f, __fmul_rn(1e-5f, fabsf(mx)));
    if (d <= thresh) {
        float4 q;
        q.x = q.y = q.z = q.w = mn;
#pragma unroll
        for (int k = 0; k < VEC_PER_THREAD; k++) {
            out[base4 + k * THREADS + tid] = q;
        }
        return;
    }

    // Lane-replicated tables: index [j*32 + lane] -> bank == lane, conflict-free.
    __shared__ float sb[17 * 32];  // bounds b_0..b_16
    __shared__ float sm[16 * 32];  // mids m_0..m_15 = 0.5*(b_j + b_{j+1})
    for (int s = tid; s < 17 * 32; s += THREADS) {
        sb[s] = bound_j(mn, d, s >> 5);
    }
    for (int s = tid; s < 16 * 32; s += THREADS) {
        int j = s >> 5;
        sm[s] = __fmul_rn(0.5f, __fadd_rn(bound_j(mn, d, j), bound_j(mn, d, j + 1)));
    }
    __syncthreads();

    const float scale = 16.0f / d;  // estimate only; corrected by exact-bound fixup

#pragma unroll
    for (int k = 0; k < VEC_PER_THREAD; k++) {
        float4 v = in[base4 + k * THREADS + tid];
        float xv[4] = {v.x, v.y, v.z, v.w};
        float qv[4];
#pragma unroll
        for (int e = 0; e < 4; e++) {
            float x = xv[e];
            int r = __float2int_rz((x - mn) * scale);
            r = min(max(r, 0), 15);
            // Enforce searchsorted(side='right') semantics against exact bounds:
            // r = #{ b_j <= x : j in 1..15 }
            while (r < 15 && sb[((r + 1) << 5) + lane] <= x) r++;
            while (r > 0 && sb[(r << 5) + lane] > x) r--;
            qv[e] = sm[(r << 5) + lane];
        }
        float4 q;
        q.x = qv[0]; q.y = qv[1]; q.z = qv[2]; q.w = qv[3];
        out[base4 + k * THREADS + tid] = q;
    }
}

extern "C" void kernel_launch(void* const* d_in, const int* in_sizes, int n_in,
                              void* d_out, int out_size) {
    const float4* in = (const float4*)d_in[0];
    float4* out = (float4*)d_out;

    init_minmax_kernel<<<1, 64>>>();
    dim3 grid(CHUNKS, ROWS);
    minmax_kernel<<<grid, THREADS>>>(in);
    quantize_kernel<<<grid, THREADS>>>(in, out);
}